// round 4
// baseline (speedup 1.0000x reference)
#include <cuda_runtime.h>

#define Dm   64
#define Km   512
#define HWm  4096
#define DHWm (Dm * HWm)          // 262144
#define NPOS 131072              // 32*64*64 positions
#define PAIRS (NPOS / 2)         // 65536
#define NDOUT (NPOS * Dm)        // 8388608 output elems for quantized
#define NBLK 148
#define NTHR 256
#define SMEM_BYTES (Km * Dm * 4 + Km * 4)   // codebook + norms = 133120 B

__device__ float g_partials[NBLK];

// fp64 direct-form distance between zf (regs) and code row in shared
__device__ __forceinline__ double dist64(const float* __restrict__ zf,
                                         const float* __restrict__ crow) {
    double acc = 0.0;
    #pragma unroll
    for (int d = 0; d < Dm; d++) {
        double t = (double)zf[d] - (double)crow[d];
        acc = fma(t, t, acc);
    }
    return acc;
}

// Pick reference-compatible argmin among the two candidates:
// exact (fp64) distances; on exact tie, lower index wins (jnp.argmin = first occurrence).
__device__ __forceinline__ int resolve2(const float* __restrict__ zf,
                                        const float* __restrict__ scb,
                                        int ia, int ib) {
    int lo = min(ia, ib), hi = max(ia, ib);
    double dlo = dist64(zf, scb + lo * Dm);
    double dhi = dist64(zf, scb + hi * Dm);
    return (dhi < dlo) ? hi : lo;
}

__global__ __launch_bounds__(NTHR, 1)
void vq_main(const float* __restrict__ z,
             const float* __restrict__ cb,
             float* __restrict__ out) {
    extern __shared__ float s[];
    float* scb = s;              // [Km*Dm]
    float* scc = s + Km * Dm;    // [Km]
    const int tid = threadIdx.x;

    // Cooperative codebook load (float4, coalesced)
    {
        const float4* src = (const float4*)cb;
        float4* dst = (float4*)scb;
        #pragma unroll 4
        for (int i = tid; i < Km * Dm / 4; i += NTHR) dst[i] = src[i];
    }
    __syncthreads();

    // Precompute code norms ||c_k||^2
    for (int c = tid; c < Km; c += NTHR) {
        const float* row = scb + c * Dm;
        float acc = 0.f;
        #pragma unroll
        for (int d = 0; d < Dm; d++) acc = fmaf(row[d], row[d], acc);
        scc[c] = acc;
    }
    __syncthreads();

    float errsum = 0.f;

    for (int p = blockIdx.x * NTHR + tid; p < PAIRS; p += NBLK * NTHR) {
        const int n0 = p;
        const int n1 = p + PAIRS;
        const int b0 = n0 >> 12, hw0 = n0 & (HWm - 1);
        const int b1 = n1 >> 12, hw1 = n1 & (HWm - 1);
        const float* zp0 = z + b0 * DHWm + hw0;
        const float* zp1 = z + b1 * DHWm + hw1;

        float zf0[Dm], zf1[Dm];
        #pragma unroll
        for (int d = 0; d < Dm; d++) {
            zf0[d] = zp0[d * HWm];   // coalesced across threads (hw contiguous)
            zf1[d] = zp1[d * HWm];
        }

        // fp32 screen: track best-2 (value, index) per position
        float b0a = 3.4e38f, b0b = 3.4e38f, b1a = 3.4e38f, b1b = 3.4e38f;
        int i0a = 0, i0b = 1, i1a = 0, i1b = 1;

        for (int k = 0; k < Km; k++) {
            const float4* c4 = (const float4*)(scb + k * Dm);
            float a00 = 0.f, a01 = 0.f, a02 = 0.f, a03 = 0.f;
            float a10 = 0.f, a11 = 0.f, a12 = 0.f, a13 = 0.f;
            #pragma unroll
            for (int i = 0; i < Dm / 4; i++) {
                const float4 cv = c4[i];   // broadcast LDS.128 (all lanes same addr)
                a00 = fmaf(zf0[4*i + 0], cv.x, a00);
                a01 = fmaf(zf0[4*i + 1], cv.y, a01);
                a02 = fmaf(zf0[4*i + 2], cv.z, a02);
                a03 = fmaf(zf0[4*i + 3], cv.w, a03);
                a10 = fmaf(zf1[4*i + 0], cv.x, a10);
                a11 = fmaf(zf1[4*i + 1], cv.y, a11);
                a12 = fmaf(zf1[4*i + 2], cv.z, a12);
                a13 = fmaf(zf1[4*i + 3], cv.w, a13);
            }
            const float dot0 = (a00 + a01) + (a02 + a03);
            const float dot1 = (a10 + a11) + (a12 + a13);
            const float d0 = fmaf(-2.f, dot0, scc[k]);
            const float d1 = fmaf(-2.f, dot1, scc[k]);

            if (d0 < b0a)      { b0b = b0a; i0b = i0a; b0a = d0; i0a = k; }
            else if (d0 < b0b) { b0b = d0; i0b = k; }
            if (d1 < b1a)      { b1b = b1a; i1b = i1a; b1a = d1; i1a = k; }
            else if (d1 < b1b) { b1b = d1; i1b = k; }
        }

        // Exact fp64 resolution of the top-2 candidates -> true argmin
        const int bi0 = resolve2(zf0, scb, i0a, i0b);
        const int bi1 = resolve2(zf1, scb, i1a, i1b);

        // Gather chosen codes, write NCHW output, accumulate exact squared error
        float* o0 = out + b0 * DHWm + hw0;
        float* o1 = out + b1 * DHWm + hw1;
        const float* q0 = scb + bi0 * Dm;
        const float* q1 = scb + bi1 * Dm;
        #pragma unroll
        for (int d = 0; d < Dm; d++) {
            const float qv0 = q0[d];
            const float qv1 = q1[d];
            o0[d * HWm] = qv0;
            o1[d * HWm] = qv1;
            const float e0 = zf0[d] - qv0;
            const float e1 = zf1[d] - qv1;
            errsum = fmaf(e0, e0, errsum);
            errsum = fmaf(e1, e1, errsum);
        }
    }

    // Deterministic block reduction of errsum
    __shared__ float red[NTHR];
    red[tid] = errsum;
    __syncthreads();
    #pragma unroll
    for (int off = NTHR / 2; off > 0; off >>= 1) {
        if (tid < off) red[tid] += red[tid + off];
        __syncthreads();
    }
    if (tid == 0) g_partials[blockIdx.x] = red[0];
}

__global__ void vq_loss(float* __restrict__ out, int out_size) {
    __shared__ float red[NTHR];
    const int tid = threadIdx.x;
    float v = 0.f;
    for (int i = tid; i < NBLK; i += NTHR) v += g_partials[i];
    red[tid] = v;
    __syncthreads();
    #pragma unroll
    for (int off = NTHR / 2; off > 0; off >>= 1) {
        if (tid < off) red[tid] += red[tid + off];
        __syncthreads();
    }
    const float loss = 1.25f * red[0] / (float)NDOUT;
    // Fill everything after the quantized tensor with the loss scalar
    for (int i = NDOUT + tid; i < out_size; i += NTHR) out[i] = loss;
}

extern "C" void kernel_launch(void* const* d_in, const int* in_sizes, int n_in,
                              void* d_out, int out_size) {
    const float* z  = (const float*)d_in[0];   // [32, 64, 64, 64] fp32 NCHW
    const float* cb = (const float*)d_in[1];   // [512, 64] fp32
    float* out = (float*)d_out;

    cudaFuncSetAttribute(vq_main, cudaFuncAttributeMaxDynamicSharedMemorySize, SMEM_BYTES);

    vq_main<<<NBLK, NTHR, SMEM_BYTES>>>(z, cb, out);
    vq_loss<<<1, NTHR>>>(out, out_size);
}

// round 7
// speedup vs baseline: 1.3422x; 1.3422x over previous
#include <cuda_runtime.h>
#include <cuda_bf16.h>
#include <cstdint>

#define Dm   64
#define Km   512
#define HWm  4096
#define DHWm (Dm * HWm)
#define NPOS 131072
#define NDOUT (NPOS * Dm)
#define NBLK 148
#define NTHR 256
#define NTILE 1024              // 131072 / 128 positions per tile
#define PITCHW 36               // smem row pitch in 32-bit words (64 bf16 + 16B pad)

// ---- SMEM layout (bytes) ----
#define OFF_BH   0                        // codebook hi bf16 [512][pitch]  (73728)
#define OFF_BL   73728                    // codebook lo bf16               (73728)
#define OFF_AH   147456                   // A tile hi bf16 [128][pitch]    (18432)
#define OFF_AL   165888                   // A tile lo                      (18432)
#define OFF_SCC  184320                   // ||c_k||^2 fp32 [512]           (2048)
#define OFF_B1V  186368                   // per-position best val   [128]
#define OFF_B1I  186880                   // per-position best idx   [128]
#define OFF_B2V  187392                   // per-position 2nd val    [128]
#define OFF_B2I  187904                   // per-position 2nd idx    [128]
#define SMEM_TOTAL 188416

__device__ float g_partials[NBLK];

__device__ __forceinline__ void mma16816(float* d, const uint32_t* a, const uint32_t* b) {
    asm volatile(
        "mma.sync.aligned.m16n8k16.row.col.f32.bf16.bf16.f32 "
        "{%0,%1,%2,%3}, {%4,%5,%6,%7}, {%8,%9}, {%0,%1,%2,%3};\n"
        : "+f"(d[0]), "+f"(d[1]), "+f"(d[2]), "+f"(d[3])
        : "r"(a[0]), "r"(a[1]), "r"(a[2]), "r"(a[3]), "r"(b[0]), "r"(b[1]));
}

__device__ __forceinline__ uint32_t pack_hi(float a, float b, float* la, float* lb) {
    __nv_bfloat16 ha = __float2bfloat16_rn(a);
    __nv_bfloat16 hb = __float2bfloat16_rn(b);
    *la = a - __bfloat162float(ha);
    *lb = b - __bfloat162float(hb);
    return ((uint32_t)__bfloat16_as_ushort(hb) << 16) | (uint32_t)__bfloat16_as_ushort(ha);
}
__device__ __forceinline__ uint32_t pack_lo(float la, float lb) {
    __nv_bfloat16 ha = __float2bfloat16_rn(la);
    __nv_bfloat16 hb = __float2bfloat16_rn(lb);
    return ((uint32_t)__bfloat16_as_ushort(hb) << 16) | (uint32_t)__bfloat16_as_ushort(ha);
}

// lexicographic (value, index) less: first-occurrence argmin semantics
__device__ __forceinline__ bool lexlt(float av, int ai, float bv, int bi) {
    return (av < bv) || (av == bv && ai < bi);
}
// merge other lane's sorted best-2 into ours (both lex-sorted)
__device__ __forceinline__ void merge2(float& v1, int& i1, float& v2, int& i2,
                                       float ov1, int oi1, float ov2, int oi2) {
    if (lexlt(ov1, oi1, v1, i1)) {
        float nv2; int ni2;
        if (lexlt(v1, i1, ov2, oi2)) { nv2 = v1; ni2 = i1; }
        else                          { nv2 = ov2; ni2 = oi2; }
        v1 = ov1; i1 = oi1; v2 = nv2; i2 = ni2;
    } else {
        if (lexlt(ov1, oi1, v2, i2)) { v2 = ov1; i2 = oi1; }
    }
}

__global__ __launch_bounds__(NTHR, 1)
void vq_mma(const float* __restrict__ z,
            const float* __restrict__ cb,
            float* __restrict__ out) {
    extern __shared__ char smem[];
    uint32_t* BH = (uint32_t*)(smem + OFF_BH);
    uint32_t* BL = (uint32_t*)(smem + OFF_BL);
    uint32_t* AH = (uint32_t*)(smem + OFF_AH);
    uint32_t* AL = (uint32_t*)(smem + OFF_AL);
    float* s_scc = (float*)(smem + OFF_SCC);
    float* s_b1v = (float*)(smem + OFF_B1V);
    int*   s_b1i = (int*)  (smem + OFF_B1I);
    float* s_b2v = (float*)(smem + OFF_B2V);
    int*   s_b2i = (int*)  (smem + OFF_B2I);

    const int tid = threadIdx.x, wid = tid >> 5, lid = tid & 31;
    const int g = lid >> 2, q = lid & 3;       // mma fragment coords
    const int wbase = wid * 16;                // this warp's 16 rows of the tile

    // ---- codebook -> SMEM bf16 hi/lo (pitch 36 words) + norms ----
    {
        const float2* cb2 = (const float2*)cb;
        for (int i = tid; i < Km * 32; i += NTHR) {
            const int row = i >> 5, dp = i & 31;
            const float2 c = cb2[row * 32 + dp];
            float la, lb;
            const uint32_t hp = pack_hi(c.x, c.y, &la, &lb);
            BH[row * PITCHW + dp] = hp;
            BL[row * PITCHW + dp] = pack_lo(la, lb);
        }
        for (int k = tid; k < Km; k += NTHR) {
            const float* row = cb + k * Dm;
            float acc = 0.f;
            #pragma unroll
            for (int d = 0; d < Dm; d++) acc = fmaf(row[d], row[d], acc);
            s_scc[k] = acc;
        }
    }
    __syncthreads();

    float errsum = 0.f;

    for (int t = blockIdx.x; t < NTILE; t += gridDim.x) {
        const int p0 = t << 7;
        const int b = p0 >> 12, hw0 = p0 & (HWm - 1);
        const float* zb = z + b * DHWm + hw0;

        // ---- stage A tile: 128 positions x 64 dims, bf16 hi/lo ----
        #pragma unroll
        for (int it = 0; it < (128 * 32) / NTHR; it++) {
            const int i = it * NTHR + tid;
            const int ap = i & 127, dp = i >> 7;
            const float z0 = zb[(2 * dp)     * HWm + ap];
            const float z1 = zb[(2 * dp + 1) * HWm + ap];
            float la, lb;
            const uint32_t hp = pack_hi(z0, z1, &la, &lb);
            AH[ap * PITCHW + dp] = hp;
            AL[ap * PITCHW + dp] = pack_lo(la, lb);
        }
        __syncthreads();

        // ---- load A fragments for this warp's 16 rows (resident) ----
        uint32_t aH[4][4], aL[4][4];
        {
            const int r0w = (wbase + g) * PITCHW;
            const int r1w = r0w + 8 * PITCHW;
            #pragma unroll
            for (int ks = 0; ks < 4; ks++) {
                const int o = ks * 8 + q;
                aH[ks][0] = AH[r0w + o];     aH[ks][1] = AH[r1w + o];
                aH[ks][2] = AH[r0w + o + 4]; aH[ks][3] = AH[r1w + o + 4];
                aL[ks][0] = AL[r0w + o];     aL[ks][1] = AL[r1w + o];
                aL[ks][2] = AL[r0w + o + 4]; aL[ks][3] = AL[r1w + o + 4];
            }
        }

        // ---- scan all 512 codes: 64 n-tiles of 8 ----
        float rAv1 = 3.4e38f, rAv2 = 3.4e38f, rBv1 = 3.4e38f, rBv2 = 3.4e38f;
        int   rAi1 = 0, rAi2 = 0, rBi1 = 0, rBi2 = 0;

        #pragma unroll 2
        for (int nt = 0; nt < 64; nt++) {
            float acc[4] = {0.f, 0.f, 0.f, 0.f};
            const int nb = (nt * 8 + g) * PITCHW;
            #pragma unroll
            for (int ks = 0; ks < 4; ks++) {
                const int o = nb + ks * 8 + q;
                uint32_t bh[2] = {BH[o], BH[o + 4]};
                uint32_t bl[2] = {BL[o], BL[o + 4]};
                mma16816(acc, aH[ks], bh);
                mma16816(acc, aL[ks], bh);
                mma16816(acc, aH[ks], bl);
            }
            const int n0 = nt * 8 + q * 2;
            const float s0 = s_scc[n0], s1 = s_scc[n0 + 1];
            const float d00 = fmaf(-2.f, acc[0], s0);
            const float d01 = fmaf(-2.f, acc[1], s1);
            const float d10 = fmaf(-2.f, acc[2], s0);
            const float d11 = fmaf(-2.f, acc[3], s1);
            // row A (pos wbase+g): cols ascending -> strict < keeps first occurrence
            if (d00 < rAv1)      { rAv2 = rAv1; rAi2 = rAi1; rAv1 = d00; rAi1 = n0; }
            else if (d00 < rAv2) { rAv2 = d00; rAi2 = n0; }
            if (d01 < rAv1)      { rAv2 = rAv1; rAi2 = rAi1; rAv1 = d01; rAi1 = n0 + 1; }
            else if (d01 < rAv2) { rAv2 = d01; rAi2 = n0 + 1; }
            // row B (pos wbase+g+8)
            if (d10 < rBv1)      { rBv2 = rBv1; rBi2 = rBi1; rBv1 = d10; rBi1 = n0; }
            else if (d10 < rBv2) { rBv2 = d10; rBi2 = n0; }
            if (d11 < rBv1)      { rBv2 = rBv1; rBi2 = rBi1; rBv1 = d11; rBi1 = n0 + 1; }
            else if (d11 < rBv2) { rBv2 = d11; rBi2 = n0 + 1; }
        }

        // ---- merge best-2 across the 4 lanes sharing each row ----
        #pragma unroll
        for (int m = 1; m <= 2; m <<= 1) {
            float ov1 = __shfl_xor_sync(0xFFFFFFFFu, rAv1, m);
            int   oi1 = __shfl_xor_sync(0xFFFFFFFFu, rAi1, m);
            float ov2 = __shfl_xor_sync(0xFFFFFFFFu, rAv2, m);
            int   oi2 = __shfl_xor_sync(0xFFFFFFFFu, rAi2, m);
            merge2(rAv1, rAi1, rAv2, rAi2, ov1, oi1, ov2, oi2);
            ov1 = __shfl_xor_sync(0xFFFFFFFFu, rBv1, m);
            oi1 = __shfl_xor_sync(0xFFFFFFFFu, rBi1, m);
            ov2 = __shfl_xor_sync(0xFFFFFFFFu, rBv2, m);
            oi2 = __shfl_xor_sync(0xFFFFFFFFu, rBi2, m);
            merge2(rBv1, rBi1, rBv2, rBi2, ov1, oi1, ov2, oi2);
        }
        if (q == 0) {
            s_b1v[wbase + g] = rAv1;     s_b1i[wbase + g] = rAi1;
            s_b2v[wbase + g] = rAv2;     s_b2i[wbase + g] = rAi2;
            s_b1v[wbase + g + 8] = rBv1; s_b1i[wbase + g + 8] = rBi1;
            s_b2v[wbase + g + 8] = rBv2; s_b2i[wbase + g + 8] = rBi2;
        }
        __syncthreads();

        // ---- epilogue: refine (if ambiguous), gather, write, errsum ----
        if (tid < 128) {
            const int pos = tid;
            const float bv = s_b1v[pos], sv = s_b2v[pos];
            int bi = s_b1i[pos];
            const int si = s_b2i[pos];

            const float* zp = zb + pos;
            float zf[Dm];
            #pragma unroll
            for (int d = 0; d < Dm; d++) zf[d] = zp[d * HWm];

            if (sv - bv < 0.05f) {   // ambiguous under screen error -> exact fp64
                const int lo = min(bi, si), hi = max(bi, si);
                const float* clo = cb + lo * Dm;
                const float* chi = cb + hi * Dm;
                double alo = 0.0, ahi = 0.0;
                #pragma unroll
                for (int d = 0; d < Dm; d++) {
                    const double tl = (double)zf[d] - (double)__ldg(clo + d);
                    const double th = (double)zf[d] - (double)__ldg(chi + d);
                    alo = fma(tl, tl, alo);
                    ahi = fma(th, th, ahi);
                }
                bi = (ahi < alo) ? hi : lo;
            }

            const float* qr = cb + bi * Dm;
            float* op = out + b * DHWm + hw0 + pos;
            #pragma unroll
            for (int d = 0; d < Dm; d++) {
                const float qv = __ldg(qr + d);
                op[d * HWm] = qv;
                const float e = zf[d] - qv;
                errsum = fmaf(e, e, errsum);
            }
        }
        __syncthreads();   // A tile + best arrays reused next iteration
    }

    // ---- deterministic block reduction of errsum ----
    __shared__ float red[NTHR];
    red[tid] = errsum;
    __syncthreads();
    #pragma unroll
    for (int off = NTHR / 2; off > 0; off >>= 1) {
        if (tid < off) red[tid] += red[tid + off];
        __syncthreads();
    }
    if (tid == 0) g_partials[blockIdx.x] = red[0];
}

__global__ void vq_loss(float* __restrict__ out, int out_size) {
    __shared__ float red[NTHR];
    const int tid = threadIdx.x;
    float v = 0.f;
    for (int i = tid; i < NBLK; i += NTHR) v += g_partials[i];
    red[tid] = v;
    __syncthreads();
    #pragma unroll
    for (int off = NTHR / 2; off > 0; off >>= 1) {
        if (tid < off) red[tid] += red[tid + off];
        __syncthreads();
    }
    const float loss = 1.25f * red[0] / (float)NDOUT;
    for (int i = NDOUT + tid; i < out_size; i += NTHR) out[i] = loss;
}

extern "C" void kernel_launch(void* const* d_in, const int* in_sizes, int n_in,
                              void* d_out, int out_size) {
    const float* z  = (const float*)d_in[0];   // [32, 64, 64, 64] fp32 NCHW
    const float* cb = (const float*)d_in[1];   // [512, 64] fp32
    float* out = (float*)d_out;

    cudaFuncSetAttribute(vq_mma, cudaFuncAttributeMaxDynamicSharedMemorySize, SMEM_TOTAL);

    vq_mma<<<NBLK, NTHR, SMEM_TOTAL>>>(z, cb, out);
    vq_loss<<<1, NTHR>>>(out, out_size);
}

// round 8
// speedup vs baseline: 1.3499x; 1.0058x over previous
#include <cuda_runtime.h>
#include <cuda_bf16.h>
#include <cstdint>

#define Dm   64
#define Km   512
#define HWm  4096
#define DHWm (Dm * HWm)
#define NPOS 131072
#define NDOUT (NPOS * Dm)
#define NBLK 148
#define NTHR 256
#define NTILE 1024              // 131072 / 128 positions per tile
#define PITCHW 36               // smem row pitch in 32-bit words (64 bf16 + 16B pad)

// ---- SMEM layout (bytes) ----
#define OFF_BH   0                        // codebook hi bf16 [512][pitch]  (73728)
#define OFF_BL   73728                    // codebook lo bf16               (73728)
#define OFF_AH   147456                   // A tile hi bf16 [128][pitch]    (18432)
#define OFF_AL   165888                   // A tile lo                      (18432)
#define OFF_SCC  184320                   // ||c_k||^2 fp32 [512]           (2048)
#define OFF_B1V  186368                   // per-position best val   [128]
#define OFF_B1I  186880                   // per-position best idx   [128]  (then final bi)
#define OFF_B2V  187392                   // per-position 2nd val    [128]
#define OFF_B2I  187904                   // per-position 2nd idx    [128]
#define SMEM_TOTAL 188416

__device__ float g_partials[NBLK];

__device__ __forceinline__ void mma16816(float* d, const uint32_t* a, const uint32_t* b) {
    asm volatile(
        "mma.sync.aligned.m16n8k16.row.col.f32.bf16.bf16.f32 "
        "{%0,%1,%2,%3}, {%4,%5,%6,%7}, {%8,%9}, {%0,%1,%2,%3};\n"
        : "+f"(d[0]), "+f"(d[1]), "+f"(d[2]), "+f"(d[3])
        : "r"(a[0]), "r"(a[1]), "r"(a[2]), "r"(a[3]), "r"(b[0]), "r"(b[1]));
}

__device__ __forceinline__ uint32_t pack_hi(float a, float b, float* la, float* lb) {
    __nv_bfloat16 ha = __float2bfloat16_rn(a);
    __nv_bfloat16 hb = __float2bfloat16_rn(b);
    *la = a - __bfloat162float(ha);
    *lb = b - __bfloat162float(hb);
    return ((uint32_t)__bfloat16_as_ushort(hb) << 16) | (uint32_t)__bfloat16_as_ushort(ha);
}
__device__ __forceinline__ uint32_t pack_lo(float la, float lb) {
    __nv_bfloat16 ha = __float2bfloat16_rn(la);
    __nv_bfloat16 hb = __float2bfloat16_rn(lb);
    return ((uint32_t)__bfloat16_as_ushort(hb) << 16) | (uint32_t)__bfloat16_as_ushort(ha);
}
__device__ __forceinline__ float lo_bf(uint32_t w) {
    return __bfloat162float(__ushort_as_bfloat16((unsigned short)(w & 0xFFFF)));
}
__device__ __forceinline__ float hi_bf(uint32_t w) {
    return __bfloat162float(__ushort_as_bfloat16((unsigned short)(w >> 16)));
}

// lexicographic (value, index) less: first-occurrence argmin semantics
__device__ __forceinline__ bool lexlt(float av, int ai, float bv, int bi) {
    return (av < bv) || (av == bv && ai < bi);
}
__device__ __forceinline__ void merge2(float& v1, int& i1, float& v2, int& i2,
                                       float ov1, int oi1, float ov2, int oi2) {
    if (lexlt(ov1, oi1, v1, i1)) {
        float nv2; int ni2;
        if (lexlt(v1, i1, ov2, oi2)) { nv2 = v1; ni2 = i1; }
        else                          { nv2 = ov2; ni2 = oi2; }
        v1 = ov1; i1 = oi1; v2 = nv2; i2 = ni2;
    } else {
        if (lexlt(ov1, oi1, v2, i2)) { v2 = ov1; i2 = oi1; }
    }
}

// Prefetch one tile's z slice for this thread (32 floats)
__device__ __forceinline__ void load_pf(const float* __restrict__ z, int t, int tid,
                                        float* __restrict__ pf) {
    const int p0 = t << 7;
    const int b = p0 >> 12, hw0 = p0 & (HWm - 1);
    const float* zb = z + b * DHWm + hw0;
    #pragma unroll
    for (int it = 0; it < 16; it++) {
        const int i = it * NTHR + tid;
        const int ap = i & 127, dp = i >> 7;
        pf[2 * it]     = zb[(2 * dp)     * HWm + ap];
        pf[2 * it + 1] = zb[(2 * dp + 1) * HWm + ap];
    }
}

__global__ __launch_bounds__(NTHR, 1)
void vq_mma(const float* __restrict__ z,
            const float* __restrict__ cb,
            float* __restrict__ out) {
    extern __shared__ char smem[];
    uint32_t* BH = (uint32_t*)(smem + OFF_BH);
    uint32_t* BL = (uint32_t*)(smem + OFF_BL);
    uint32_t* AH = (uint32_t*)(smem + OFF_AH);
    uint32_t* AL = (uint32_t*)(smem + OFF_AL);
    float* s_scc = (float*)(smem + OFF_SCC);
    float* s_b1v = (float*)(smem + OFF_B1V);
    int*   s_b1i = (int*)  (smem + OFF_B1I);
    float* s_b2v = (float*)(smem + OFF_B2V);
    int*   s_b2i = (int*)  (smem + OFF_B2I);

    const int tid = threadIdx.x, wid = tid >> 5, lid = tid & 31;
    const int g = lid >> 2, q = lid & 3;       // mma fragment coords
    const int wbase = wid * 16;                // this warp's 16 rows of the tile

    // ---- codebook -> SMEM bf16 hi/lo (pitch 36 words) + norms ----
    {
        const float2* cb2 = (const float2*)cb;
        for (int i = tid; i < Km * 32; i += NTHR) {
            const int row = i >> 5, dp = i & 31;
            const float2 c = cb2[row * 32 + dp];
            float la, lb;
            const uint32_t hp = pack_hi(c.x, c.y, &la, &lb);
            BH[row * PITCHW + dp] = hp;
            BL[row * PITCHW + dp] = pack_lo(la, lb);
        }
        for (int k = tid; k < Km; k += NTHR) {
            const float* row = cb + k * Dm;
            float acc = 0.f;
            #pragma unroll
            for (int d = 0; d < Dm; d++) acc = fmaf(row[d], row[d], acc);
            s_scc[k] = acc;
        }
    }
    __syncthreads();

    float errsum = 0.f;
    float pf[32];
    int t = blockIdx.x;
    if (t < NTILE) load_pf(z, t, tid, pf);

    for (; t < NTILE; t += NBLK) {
        const int p0 = t << 7;
        const int b = p0 >> 12, hw0 = p0 & (HWm - 1);
        const float* zb = z + b * DHWm + hw0;

        // ---- stage A tile from prefetch registers (no gmem wait) ----
        #pragma unroll
        for (int it = 0; it < 16; it++) {
            const int i = it * NTHR + tid;
            const int ap = i & 127, dp = i >> 7;
            float la, lb;
            const uint32_t hp = pack_hi(pf[2 * it], pf[2 * it + 1], &la, &lb);
            AH[ap * PITCHW + dp] = hp;
            AL[ap * PITCHW + dp] = pack_lo(la, lb);
        }
        __syncthreads();

        // ---- load A fragments for this warp's 16 rows (resident) ----
        uint32_t aH[4][4], aL[4][4];
        {
            const int r0w = (wbase + g) * PITCHW;
            const int r1w = r0w + 8 * PITCHW;
            #pragma unroll
            for (int ks = 0; ks < 4; ks++) {
                const int o = ks * 8 + q;
                aH[ks][0] = AH[r0w + o];     aH[ks][1] = AH[r1w + o];
                aH[ks][2] = AH[r0w + o + 4]; aH[ks][3] = AH[r1w + o + 4];
                aL[ks][0] = AL[r0w + o];     aL[ks][1] = AL[r1w + o];
                aL[ks][2] = AL[r0w + o + 4]; aL[ks][3] = AL[r1w + o + 4];
            }
        }

        // ---- prefetch NEXT tile's z (latency hidden under the scan) ----
        const int tn = t + NBLK;
        if (tn < NTILE) load_pf(z, tn, tid, pf);

        // ---- scan all 512 codes: 64 n-tiles of 8 ----
        float rAv1 = 3.4e38f, rAv2 = 3.4e38f, rBv1 = 3.4e38f, rBv2 = 3.4e38f;
        int   rAi1 = 0, rAi2 = 0, rBi1 = 0, rBi2 = 0;

        #pragma unroll 2
        for (int nt = 0; nt < 64; nt++) {
            float acc[4] = {0.f, 0.f, 0.f, 0.f};
            const int nb = (nt * 8 + g) * PITCHW;
            #pragma unroll
            for (int ks = 0; ks < 4; ks++) {
                const int o = nb + ks * 8 + q;
                uint32_t bh[2] = {BH[o], BH[o + 4]};
                uint32_t bl[2] = {BL[o], BL[o + 4]};
                mma16816(acc, aH[ks], bh);
                mma16816(acc, aL[ks], bh);
                mma16816(acc, aH[ks], bl);
            }
            const int n0 = nt * 8 + q * 2;
            const float2 sc = *(const float2*)&s_scc[n0];
            const float d00 = fmaf(-2.f, acc[0], sc.x);
            const float d01 = fmaf(-2.f, acc[1], sc.y);
            const float d10 = fmaf(-2.f, acc[2], sc.x);
            const float d11 = fmaf(-2.f, acc[3], sc.y);
            if (d00 < rAv1)      { rAv2 = rAv1; rAi2 = rAi1; rAv1 = d00; rAi1 = n0; }
            else if (d00 < rAv2) { rAv2 = d00; rAi2 = n0; }
            if (d01 < rAv1)      { rAv2 = rAv1; rAi2 = rAi1; rAv1 = d01; rAi1 = n0 + 1; }
            else if (d01 < rAv2) { rAv2 = d01; rAi2 = n0 + 1; }
            if (d10 < rBv1)      { rBv2 = rBv1; rBi2 = rBi1; rBv1 = d10; rBi1 = n0; }
            else if (d10 < rBv2) { rBv2 = d10; rBi2 = n0; }
            if (d11 < rBv1)      { rBv2 = rBv1; rBi2 = rBi1; rBv1 = d11; rBi1 = n0 + 1; }
            else if (d11 < rBv2) { rBv2 = d11; rBi2 = n0 + 1; }
        }

        // ---- merge best-2 across the 4 lanes sharing each row ----
        #pragma unroll
        for (int m = 1; m <= 2; m <<= 1) {
            float ov1 = __shfl_xor_sync(0xFFFFFFFFu, rAv1, m);
            int   oi1 = __shfl_xor_sync(0xFFFFFFFFu, rAi1, m);
            float ov2 = __shfl_xor_sync(0xFFFFFFFFu, rAv2, m);
            int   oi2 = __shfl_xor_sync(0xFFFFFFFFu, rAi2, m);
            merge2(rAv1, rAi1, rAv2, rAi2, ov1, oi1, ov2, oi2);
            ov1 = __shfl_xor_sync(0xFFFFFFFFu, rBv1, m);
            oi1 = __shfl_xor_sync(0xFFFFFFFFu, rBi1, m);
            ov2 = __shfl_xor_sync(0xFFFFFFFFu, rBv2, m);
            oi2 = __shfl_xor_sync(0xFFFFFFFFu, rBi2, m);
            merge2(rBv1, rBi1, rBv2, rBi2, ov1, oi1, ov2, oi2);
        }
        if (q == 0) {
            s_b1v[wbase + g] = rAv1;     s_b1i[wbase + g] = rAi1;
            s_b2v[wbase + g] = rAv2;     s_b2i[wbase + g] = rAi2;
            s_b1v[wbase + g + 8] = rBv1; s_b1i[wbase + g + 8] = rBi1;
            s_b2v[wbase + g + 8] = rBv2; s_b2i[wbase + g + 8] = rBi2;
        }
        __syncthreads();

        // ---- phase 1: decide final index (rare exact fp64 refine) ----
        if (tid < 128) {
            const int pos = tid;
            const float bv = s_b1v[pos], sv = s_b2v[pos];
            int bi = s_b1i[pos];
            const int si = s_b2i[pos];
            if (sv - bv < 0.05f) {   // ambiguous under screen error -> exact fp64
                const float* zp = zb + pos;
                float zf[Dm];
                #pragma unroll
                for (int d = 0; d < Dm; d++) zf[d] = zp[d * HWm];
                const int lo = min(bi, si), hi = max(bi, si);
                const float* clo = cb + lo * Dm;
                const float* chi = cb + hi * Dm;
                double alo = 0.0, ahi = 0.0;
                #pragma unroll
                for (int d = 0; d < Dm; d++) {
                    const double tl = (double)zf[d] - (double)__ldg(clo + d);
                    const double th = (double)zf[d] - (double)__ldg(chi + d);
                    alo = fma(tl, tl, alo);
                    ahi = fma(th, th, ahi);
                }
                bi = (ahi < alo) ? hi : lo;
            }
            s_b1i[pos] = bi;   // publish final index
        }
        __syncthreads();

        // ---- phase 2: all 256 threads gather q, write, errsum ----
        {
            const int pos = tid & 127, h = tid >> 7;
            const int bi = s_b1i[pos];
            const float2* qr = (const float2*)(cb + bi * Dm + h * 32);
            float* op = out + b * DHWm + hw0 + pos;
            const uint32_t* ahp = AH + pos * PITCHW + h * 16;
            const uint32_t* alp = AL + pos * PITCHW + h * 16;
            #pragma unroll
            for (int jp = 0; jp < 16; jp++) {
                const uint32_t hw_ = ahp[jp];
                const uint32_t lw_ = alp[jp];
                const float z0 = lo_bf(hw_) + lo_bf(lw_);   // zf reconstruct (err ~2^-18)
                const float z1 = hi_bf(hw_) + hi_bf(lw_);
                const float2 qv = __ldg(qr + jp);
                const int d = h * 32 + 2 * jp;
                op[d * HWm]       = qv.x;
                op[(d + 1) * HWm] = qv.y;
                const float e0 = z0 - qv.x;
                const float e1 = z1 - qv.y;
                errsum = fmaf(e0, e0, errsum);
                errsum = fmaf(e1, e1, errsum);
            }
        }
        __syncthreads();   // A tile + best arrays reused next iteration
    }

    // ---- deterministic block reduction of errsum ----
    __shared__ float red[NTHR];
    red[tid] = errsum;
    __syncthreads();
    #pragma unroll
    for (int off = NTHR / 2; off > 0; off >>= 1) {
        if (tid < off) red[tid] += red[tid + off];
        __syncthreads();
    }
    if (tid == 0) g_partials[blockIdx.x] = red[0];
}

__global__ void vq_loss(float* __restrict__ out, int out_size) {
    __shared__ float red[NTHR];
    const int tid = threadIdx.x;
    float v = 0.f;
    for (int i = tid; i < NBLK; i += NTHR) v += g_partials[i];
    red[tid] = v;
    __syncthreads();
    #pragma unroll
    for (int off = NTHR / 2; off > 0; off >>= 1) {
        if (tid < off) red[tid] += red[tid + off];
        __syncthreads();
    }
    const float loss = 1.25f * red[0] / (float)NDOUT;
    for (int i = NDOUT + tid; i < out_size; i += NTHR) out[i] = loss;
}

extern "C" void kernel_launch(void* const* d_in, const int* in_sizes, int n_in,
                              void* d_out, int out_size) {
    const float* z  = (const float*)d_in[0];   // [32, 64, 64, 64] fp32 NCHW
    const float* cb = (const float*)d_in[1];   // [512, 64] fp32
    float* out = (float*)d_out;

    cudaFuncSetAttribute(vq_mma, cudaFuncAttributeMaxDynamicSharedMemorySize, SMEM_TOTAL);

    vq_mma<<<NBLK, NTHR, SMEM_TOTAL>>>(z, cb, out);
    vq_loss<<<1, NTHR>>>(out, out_size);
}

// round 9
// speedup vs baseline: 1.4698x; 1.0888x over previous
#include <cuda_runtime.h>
#include <cuda_bf16.h>
#include <cstdint>

#define Dm   64
#define Km   512
#define HWm  4096
#define DHWm (Dm * HWm)
#define NPOS 131072
#define NDOUT (NPOS * Dm)
#define NBLK 148
#define NTHR 256
#define NTILE 1024              // 131072 / 128 positions per tile
#define PITCHW 36               // A smem row pitch in words (64 bf16 + 16B pad)

// ---- SMEM layout (bytes) ----
#define OFF_BH2  0                        // B hi, fragment-ordered [64nt][4ks][32ln][2w] (65536)
#define OFF_BL2  65536                    // B lo, fragment-ordered                       (65536)
#define OFF_AH   131072                   // A tile hi bf16 [128][PITCHW]                 (18432)
#define OFF_AL   149504                   // A tile lo                                    (18432)
#define OFF_SCC  167936                   // ||c_k||^2 fp32 [512]                         (2048)
#define OFF_B1V  169984                   // per-position best val [128]
#define OFF_B1I  170496                   // per-position best idx [128] (then final bi)
#define OFF_B2V  171008
#define OFF_B2I  171520
#define SMEM_TOTAL 172032

__device__ float g_partials[NBLK];

__device__ __forceinline__ void mma16816(float* d, const uint32_t* a, const uint32_t* b) {
    asm volatile(
        "mma.sync.aligned.m16n8k16.row.col.f32.bf16.bf16.f32 "
        "{%0,%1,%2,%3}, {%4,%5,%6,%7}, {%8,%9}, {%0,%1,%2,%3};\n"
        : "+f"(d[0]), "+f"(d[1]), "+f"(d[2]), "+f"(d[3])
        : "r"(a[0]), "r"(a[1]), "r"(a[2]), "r"(a[3]), "r"(b[0]), "r"(b[1]));
}

__device__ __forceinline__ uint32_t pack_hi(float a, float b, float* la, float* lb) {
    __nv_bfloat16 ha = __float2bfloat16_rn(a);
    __nv_bfloat16 hb = __float2bfloat16_rn(b);
    *la = a - __bfloat162float(ha);
    *lb = b - __bfloat162float(hb);
    return ((uint32_t)__bfloat16_as_ushort(hb) << 16) | (uint32_t)__bfloat16_as_ushort(ha);
}
__device__ __forceinline__ uint32_t pack_lo(float la, float lb) {
    __nv_bfloat16 ha = __float2bfloat16_rn(la);
    __nv_bfloat16 hb = __float2bfloat16_rn(lb);
    return ((uint32_t)__bfloat16_as_ushort(hb) << 16) | (uint32_t)__bfloat16_as_ushort(ha);
}
__device__ __forceinline__ float lo_bf(uint32_t w) {
    return __bfloat162float(__ushort_as_bfloat16((unsigned short)(w & 0xFFFF)));
}
__device__ __forceinline__ float hi_bf(uint32_t w) {
    return __bfloat162float(__ushort_as_bfloat16((unsigned short)(w >> 16)));
}

// lexicographic (value, index) less: first-occurrence argmin semantics
__device__ __forceinline__ bool lexlt(float av, int ai, float bv, int bi) {
    return (av < bv) || (av == bv && ai < bi);
}
__device__ __forceinline__ void merge2(float& v1, int& i1, float& v2, int& i2,
                                       float ov1, int oi1, float ov2, int oi2) {
    if (lexlt(ov1, oi1, v1, i1)) {
        float nv2; int ni2;
        if (lexlt(v1, i1, ov2, oi2)) { nv2 = v1; ni2 = i1; }
        else                          { nv2 = ov2; ni2 = oi2; }
        v1 = ov1; i1 = oi1; v2 = nv2; i2 = ni2;
    } else {
        if (lexlt(ov1, oi1, v2, i2)) { v2 = ov1; i2 = oi1; }
    }
}

// Prefetch one tile's z slice for this thread (32 floats)
__device__ __forceinline__ void load_pf(const float* __restrict__ z, int t, int tid,
                                        float* __restrict__ pf) {
    const int p0 = t << 7;
    const int b = p0 >> 12, hw0 = p0 & (HWm - 1);
    const float* zb = z + b * DHWm + hw0;
    #pragma unroll
    for (int it = 0; it < 16; it++) {
        const int i = it * NTHR + tid;
        const int ap = i & 127, dp = i >> 7;
        pf[2 * it]     = zb[(2 * dp)     * HWm + ap];
        pf[2 * it + 1] = zb[(2 * dp + 1) * HWm + ap];
    }
}

__global__ __launch_bounds__(NTHR, 1)
void vq_mma(const float* __restrict__ z,
            const float* __restrict__ cb,
            float* __restrict__ out) {
    extern __shared__ char smem[];
    uint2* BH2 = (uint2*)(smem + OFF_BH2);
    uint2* BL2 = (uint2*)(smem + OFF_BL2);
    uint32_t* AH = (uint32_t*)(smem + OFF_AH);
    uint32_t* AL = (uint32_t*)(smem + OFF_AL);
    float* s_scc = (float*)(smem + OFF_SCC);
    float* s_b1v = (float*)(smem + OFF_B1V);
    int*   s_b1i = (int*)  (smem + OFF_B1I);
    float* s_b2v = (float*)(smem + OFF_B2V);
    int*   s_b2i = (int*)  (smem + OFF_B2I);

    const int tid = threadIdx.x, wid = tid >> 5, lid = tid & 31;
    const int g = lid >> 2, q = lid & 3;       // mma fragment coords
    const int wbase = wid * 16;                // this warp's 16 rows of the tile

    // ---- codebook -> fragment-ordered smem bf16 hi/lo + norms ----
    // Fragment (nt, ks, lane): code row r = nt*8+g; words = dims (d0,d0+1),(d0+8,d0+9), d0=16ks+2q
    for (int j = tid; j < 64 * 4 * 32; j += NTHR) {
        const int l = j & 31, ks = (j >> 5) & 3, nt = j >> 7;
        const int gg = l >> 2, qq = l & 3;
        const int r = nt * 8 + gg;
        const int d0 = ks * 16 + qq * 2;
        const float2 c0 = *(const float2*)(cb + r * Dm + d0);
        const float2 c1 = *(const float2*)(cb + r * Dm + d0 + 8);
        float la, lb;
        const uint32_t h0 = pack_hi(c0.x, c0.y, &la, &lb);
        const uint32_t l0 = pack_lo(la, lb);
        const uint32_t h1 = pack_hi(c1.x, c1.y, &la, &lb);
        const uint32_t l1 = pack_lo(la, lb);
        BH2[j] = make_uint2(h0, h1);
        BL2[j] = make_uint2(l0, l1);
    }
    for (int k = tid; k < Km; k += NTHR) {
        const float* row = cb + k * Dm;
        float acc = 0.f;
        #pragma unroll
        for (int d = 0; d < Dm; d++) acc = fmaf(row[d], row[d], acc);
        s_scc[k] = acc;
    }
    __syncthreads();

    float errsum = 0.f;
    float pf[32];
    int t = blockIdx.x;
    if (t < NTILE) load_pf(z, t, tid, pf);

    for (; t < NTILE; t += NBLK) {
        const int p0 = t << 7;
        const int b = p0 >> 12, hw0 = p0 & (HWm - 1);
        const float* zb = z + b * DHWm + hw0;

        // ---- stage A tile from prefetch registers ----
        #pragma unroll
        for (int it = 0; it < 16; it++) {
            const int i = it * NTHR + tid;
            const int ap = i & 127, dp = i >> 7;
            float la, lb;
            const uint32_t hp = pack_hi(pf[2 * it], pf[2 * it + 1], &la, &lb);
            AH[ap * PITCHW + dp] = hp;
            AL[ap * PITCHW + dp] = pack_lo(la, lb);
        }
        __syncthreads();

        // ---- load A fragments (resident) ----
        uint32_t aH[4][4], aL[4][4];
        {
            const int r0w = (wbase + g) * PITCHW;
            const int r1w = r0w + 8 * PITCHW;
            #pragma unroll
            for (int ks = 0; ks < 4; ks++) {
                const int o = ks * 8 + q;
                aH[ks][0] = AH[r0w + o];     aH[ks][1] = AH[r1w + o];
                aH[ks][2] = AH[r0w + o + 4]; aH[ks][3] = AH[r1w + o + 4];
                aL[ks][0] = AL[r0w + o];     aL[ks][1] = AL[r1w + o];
                aL[ks][2] = AL[r0w + o + 4]; aL[ks][3] = AL[r1w + o + 4];
            }
        }

        // ---- prefetch NEXT tile's z (hidden under scan) ----
        const int tn = t + NBLK;
        if (tn < NTILE) load_pf(z, tn, tid, pf);

        // ---- scan all 512 codes: 64 n-tiles; 3 independent acc chains of depth 4 ----
        float rAv1 = 3.4e38f, rAv2 = 3.4e38f, rBv1 = 3.4e38f, rBv2 = 3.4e38f;
        int   rAi1 = 0, rAi2 = 0, rBi1 = 0, rBi2 = 0;

        #pragma unroll 2
        for (int nt = 0; nt < 64; nt++) {
            float aHH[4] = {0.f, 0.f, 0.f, 0.f};
            float aLH[4] = {0.f, 0.f, 0.f, 0.f};
            float aHL[4] = {0.f, 0.f, 0.f, 0.f};
            const int fb = nt * 4 * 32 + lid;
            #pragma unroll
            for (int ks = 0; ks < 4; ks++) {
                const uint2 bh = BH2[fb + ks * 32];   // one LDS.64, conflict-free
                const uint2 bl = BL2[fb + ks * 32];
                mma16816(aHH, aH[ks], (const uint32_t*)&bh);
                mma16816(aLH, aL[ks], (const uint32_t*)&bh);
                mma16816(aHL, aH[ks], (const uint32_t*)&bl);
            }
            const int n0 = nt * 8 + q * 2;
            const float2 sc = *(const float2*)&s_scc[n0];
            const float d00 = fmaf(-2.f, (aHH[0] + aLH[0]) + aHL[0], sc.x);
            const float d01 = fmaf(-2.f, (aHH[1] + aLH[1]) + aHL[1], sc.y);
            const float d10 = fmaf(-2.f, (aHH[2] + aLH[2]) + aHL[2], sc.x);
            const float d11 = fmaf(-2.f, (aHH[3] + aLH[3]) + aHL[3], sc.y);
            if (d00 < rAv1)      { rAv2 = rAv1; rAi2 = rAi1; rAv1 = d00; rAi1 = n0; }
            else if (d00 < rAv2) { rAv2 = d00; rAi2 = n0; }
            if (d01 < rAv1)      { rAv2 = rAv1; rAi2 = rAi1; rAv1 = d01; rAi1 = n0 + 1; }
            else if (d01 < rAv2) { rAv2 = d01; rAi2 = n0 + 1; }
            if (d10 < rBv1)      { rBv2 = rBv1; rBi2 = rBi1; rBv1 = d10; rBi1 = n0; }
            else if (d10 < rBv2) { rBv2 = d10; rBi2 = n0; }
            if (d11 < rBv1)      { rBv2 = rBv1; rBi2 = rBi1; rBv1 = d11; rBi1 = n0 + 1; }
            else if (d11 < rBv2) { rBv2 = d11; rBi2 = n0 + 1; }
        }

        // ---- merge best-2 across the 4 lanes sharing each row ----
        #pragma unroll
        for (int m = 1; m <= 2; m <<= 1) {
            float ov1 = __shfl_xor_sync(0xFFFFFFFFu, rAv1, m);
            int   oi1 = __shfl_xor_sync(0xFFFFFFFFu, rAi1, m);
            float ov2 = __shfl_xor_sync(0xFFFFFFFFu, rAv2, m);
            int   oi2 = __shfl_xor_sync(0xFFFFFFFFu, rAi2, m);
            merge2(rAv1, rAi1, rAv2, rAi2, ov1, oi1, ov2, oi2);
            ov1 = __shfl_xor_sync(0xFFFFFFFFu, rBv1, m);
            oi1 = __shfl_xor_sync(0xFFFFFFFFu, rBi1, m);
            ov2 = __shfl_xor_sync(0xFFFFFFFFu, rBv2, m);
            oi2 = __shfl_xor_sync(0xFFFFFFFFu, rBi2, m);
            merge2(rBv1, rBi1, rBv2, rBi2, ov1, oi1, ov2, oi2);
        }
        if (q == 0) {
            s_b1v[wbase + g] = rAv1;     s_b1i[wbase + g] = rAi1;
            s_b2v[wbase + g] = rAv2;     s_b2i[wbase + g] = rAi2;
            s_b1v[wbase + g + 8] = rBv1; s_b1i[wbase + g + 8] = rBi1;
            s_b2v[wbase + g + 8] = rBv2; s_b2i[wbase + g + 8] = rBi2;
        }
        __syncthreads();

        // ---- phase 1: decide final index (rare exact fp64 refine) ----
        if (tid < 128) {
            const int pos = tid;
            const float bv = s_b1v[pos], sv = s_b2v[pos];
            int bi = s_b1i[pos];
            const int si = s_b2i[pos];
            if (sv - bv < 0.05f) {   // ambiguous under screen error -> exact fp64
                const float* zp = zb + pos;
                float zf[Dm];
                #pragma unroll
                for (int d = 0; d < Dm; d++) zf[d] = zp[d * HWm];
                const int lo = min(bi, si), hi = max(bi, si);
                const float* clo = cb + lo * Dm;
                const float* chi = cb + hi * Dm;
                double alo = 0.0, ahi = 0.0;
                #pragma unroll
                for (int d = 0; d < Dm; d++) {
                    const double tl = (double)zf[d] - (double)__ldg(clo + d);
                    const double th = (double)zf[d] - (double)__ldg(chi + d);
                    alo = fma(tl, tl, alo);
                    ahi = fma(th, th, ahi);
                }
                bi = (ahi < alo) ? hi : lo;
            }
            s_b1i[pos] = bi;   // publish final index
        }
        __syncthreads();

        // ---- phase 2: all 256 threads gather q, write, errsum ----
        {
            const int pos = tid & 127, h = tid >> 7;
            const int bi = s_b1i[pos];
            const float2* qr = (const float2*)(cb + bi * Dm + h * 32);
            float* op = out + b * DHWm + hw0 + pos;
            const uint32_t* ahp = AH + pos * PITCHW + h * 16;
            const uint32_t* alp = AL + pos * PITCHW + h * 16;
            #pragma unroll
            for (int jp = 0; jp < 16; jp++) {
                const uint32_t hw_ = ahp[jp];
                const uint32_t lw_ = alp[jp];
                const float z0 = lo_bf(hw_) + lo_bf(lw_);   // zf reconstruct (err ~2^-18)
                const float z1 = hi_bf(hw_) + hi_bf(lw_);
                const float2 qv = __ldg(qr + jp);
                const int d = h * 32 + 2 * jp;
                op[d * HWm]       = qv.x;
                op[(d + 1) * HWm] = qv.y;
                const float e0 = z0 - qv.x;
                const float e1 = z1 - qv.y;
                errsum = fmaf(e0, e0, errsum);
                errsum = fmaf(e1, e1, errsum);
            }
        }
        __syncthreads();   // A tile + best arrays reused next iteration
    }

    // ---- deterministic block reduction of errsum ----
    __shared__ float red[NTHR];
    red[tid] = errsum;
    __syncthreads();
    #pragma unroll
    for (int off = NTHR / 2; off > 0; off >>= 1) {
        if (tid < off) red[tid] += red[tid + off];
        __syncthreads();
    }
    if (tid == 0) g_partials[blockIdx.x] = red[0];
}

__global__ void vq_loss(float* __restrict__ out, int out_size) {
    __shared__ float red[NTHR];
    const int tid = threadIdx.x;
    float v = 0.f;
    for (int i = tid; i < NBLK; i += NTHR) v += g_partials[i];
    red[tid] = v;
    __syncthreads();
    #pragma unroll
    for (int off = NTHR / 2; off > 0; off >>= 1) {
        if (tid < off) red[tid] += red[tid + off];
        __syncthreads();
    }
    const float loss = 1.25f * red[0] / (float)NDOUT;
    for (int i = NDOUT + tid; i < out_size; i += NTHR) out[i] = loss;
}

extern "C" void kernel_launch(void* const* d_in, const int* in_sizes, int n_in,
                              void* d_out, int out_size) {
    const float* z  = (const float*)d_in[0];   // [32, 64, 64, 64] fp32 NCHW
    const float* cb = (const float*)d_in[1];   // [512, 64] fp32
    float* out = (float*)d_out;

    cudaFuncSetAttribute(vq_mma, cudaFuncAttributeMaxDynamicSharedMemorySize, SMEM_TOTAL);

    vq_mma<<<NBLK, NTHR, SMEM_TOTAL>>>(z, cb, out);
    vq_loss<<<1, NTHR>>>(out, out_size);
}